// round 1
// baseline (speedup 1.0000x reference)
#include <cuda_runtime.h>
#include <math.h>

#define NT 256
#define NB_TOK 17
#define DIMX 256

// ---- graph constants -------------------------------------------------------
__constant__ int   c_adj[17]  = {0x93,0x7,0xE,0xC,0x31,0x70,0x60,0x181,0x4B80,
                                 0x700,0x600,0x1900,0x3800,0x3000,0xC100,0x1C000,0x18000};
__constant__ float c_deg[17]  = {4,3,3,2,3,3,2,3,5,3,2,3,3,2,3,3,2};
__constant__ int   c_hop[17]  = {0,1,4,7,2,5,8,3,6,9,11,14,10,12,15,13,16};
__constant__ int   c_graph[17]= {0,1,4,7,2,5,8,3,6,9,12,10,13,15,11,14,16};
__constant__ int   c_bpe[17]  = {0,1,2,0,1,2,0,1,2,0,3,4,0,3,4,3,4};

struct Params {
    const float *x;
    const float *gcn_ln_g, *gcn_ln_b;
    const float *gcn_w1, *gcn_b1, *gcn_w2, *gcn_b2;
    const float *bp;
    const float *ssm_ln_g, *ssm_ln_b;
    const float *in_proj_w;
    const float *conv_w, *conv_b;
    const float *x_proj_w;
    const float *dt_proj_w, *dt_proj_b;
    const float *A_log, *Dp, *out_proj_w;
    const float *ln1_g, *ln1_b;
    const float *qkv_w, *attn_proj_w, *attn_proj_b;
    const float *ln2_g, *ln2_b;
    const float *mlp_w1, *mlp_b1, *mlp_w2, *mlp_b2;
    float *out;
    int nb;
};

struct Smem {
    float res[17*256];    // residual / evolving x
    float cur[17*256];    // working 256-wide buffer
    float big[17*1024];   // xz / qkv / mlp hidden / 256|512 temps
    float b512[17*512];   // gcn hidden / ssm y / t_o
    float dbl[17*24];
    float ahat[17*17];
};

__device__ __forceinline__ float gelu_t(float x) {
    float x3 = x*x*x;
    return 0.5f*x*(1.f + tanhf(0.7978845608028654f*(x + 0.044715f*x3)));
}
__device__ __forceinline__ float silu_f(float x) { return x / (1.f + expf(-x)); }
__device__ __forceinline__ float softplus_f(float x) { return x > 20.f ? x : log1pf(expf(x)); }

// out[17][OUTS(n<N)] = ACT( in[17][INS] @ W[K][N] + bias[N] )
template<int K, int N, int INS, int OUTS, int ACT>
__device__ __forceinline__ void gemm17(const float* __restrict__ in,
                                       const float* __restrict__ W,
                                       const float* __restrict__ bias,
                                       float* __restrict__ out)
{
#pragma unroll 1
    for (int n0 = 0; n0 < N; n0 += NT) {
        const int n = n0 + threadIdx.x;
        float acc[17];
        const float bv = bias ? __ldg(bias + n) : 0.f;
#pragma unroll
        for (int l = 0; l < 17; ++l) acc[l] = bv;
#pragma unroll 1
        for (int k = 0; k < K; k += 4) {
            const float w0 = __ldg(W + (size_t)(k+0)*N + n);
            const float w1 = __ldg(W + (size_t)(k+1)*N + n);
            const float w2 = __ldg(W + (size_t)(k+2)*N + n);
            const float w3 = __ldg(W + (size_t)(k+3)*N + n);
#pragma unroll
            for (int l = 0; l < 17; ++l) {
                const float4 iv = *reinterpret_cast<const float4*>(in + l*INS + k);
                acc[l] = fmaf(iv.x, w0, acc[l]);
                acc[l] = fmaf(iv.y, w1, acc[l]);
                acc[l] = fmaf(iv.z, w2, acc[l]);
                acc[l] = fmaf(iv.w, w3, acc[l]);
            }
        }
#pragma unroll
        for (int l = 0; l < 17; ++l) {
            float v = acc[l];
            if (ACT == 1) v = gelu_t(v);
            out[l*OUTS + n] = v;
        }
    }
}

// layernorm over last dim 256; src/dst stride 256 (warp per row)
__device__ __forceinline__ void ln17(const float* __restrict__ src, float* __restrict__ dst,
                                     const float* __restrict__ g, const float* __restrict__ b)
{
    const int w = threadIdx.x >> 5, lane = threadIdx.x & 31;
    for (int l = w; l < 17; l += 8) {
        const float* row = src + l*256;
        float s = 0.f;
#pragma unroll
        for (int i = 0; i < 8; ++i) s += row[lane + 32*i];
#pragma unroll
        for (int o = 16; o; o >>= 1) s += __shfl_xor_sync(0xffffffffu, s, o);
        const float m = s * (1.f/256.f);
        float v = 0.f;
#pragma unroll
        for (int i = 0; i < 8; ++i) { float d = row[lane+32*i]-m; v = fmaf(d,d,v); }
#pragma unroll
        for (int o = 16; o; o >>= 1) v += __shfl_xor_sync(0xffffffffu, v, o);
        const float r = rsqrtf(v*(1.f/256.f) + 1e-5f);
#pragma unroll
        for (int i = 0; i < 8; ++i) {
            int c = lane + 32*i;
            dst[l*256+c] = (row[c]-m)*r*__ldg(g+c) + __ldg(b+c);
        }
    }
}

// out[i][d] = sum_j ahat[i][j] * in[j][d]   (strides = D)
template<int D>
__device__ __forceinline__ void mix17(const float* __restrict__ in, float* __restrict__ out,
                                      const float* __restrict__ ah)
{
#pragma unroll 1
    for (int d0 = 0; d0 < D; d0 += NT) {
        const int d = d0 + threadIdx.x;
        float v[17];
#pragma unroll
        for (int j = 0; j < 17; ++j) v[j] = in[j*D + d];
#pragma unroll 1
        for (int i = 0; i < 17; ++i) {
            float a = 0.f;
#pragma unroll
            for (int j = 0; j < 17; ++j) a = fmaf(ah[i*17+j], v[j], a);
            out[i*D + d] = a;
        }
    }
}

__global__ void __launch_bounds__(NT, 1)
block_kernel(Params P)
{
    extern __shared__ float smraw[];
    Smem* S = reinterpret_cast<Smem*>(smraw);
    const int tid = threadIdx.x;
    const int b = blockIdx.x;
    if (b >= P.nb) return;

    // ---- load x -> res; build A_HAT ----
    {
        const float4* xin = reinterpret_cast<const float4*>(P.x + (size_t)b*4352);
        float4* rr = reinterpret_cast<float4*>(S->res);
        for (int i = tid; i < 1088; i += NT) rr[i] = xin[i];
        for (int t = tid; t < 289; t += NT) {
            int i = t/17, j = t - i*17;
            S->ahat[t] = ((c_adj[i]>>j)&1) ? rsqrtf(c_deg[i]*c_deg[j]) : 0.f;
        }
    }
    __syncthreads();

    // ================= Stage A: GCN =================
    ln17(S->res, S->cur, P.gcn_ln_g, P.gcn_ln_b);
    __syncthreads();
    mix17<256>(S->cur, S->big, S->ahat);                       // tA = big[17][256]
    __syncthreads();
    gemm17<256,512,256,512,1>(S->big, P.gcn_w1, P.gcn_b1, S->b512);  // gelu
    __syncthreads();
    mix17<512>(S->b512, S->big, S->ahat);                      // t5 = big[17][512]
    __syncthreads();
    gemm17<512,256,512,256,0>(S->big, P.gcn_w2, P.gcn_b2, S->cur);
    __syncthreads();
    for (int t = tid; t < 4352; t += NT) S->res[t] += S->cur[t];   // x = res + h  (res1)
    __syncthreads();

    // ================= Stage B: SSM (mamba) =================
    // build xs = x[HOP] + bpe -> tA
    for (int t = tid; t < 4352; t += NT) {
        int l = t >> 8, d = t & 255;
        S->big[l*256 + d] = S->res[c_hop[l]*256 + d] + __ldg(P.bp + c_bpe[l]*256 + d);
    }
    __syncthreads();
    ln17(S->big, S->cur, P.ssm_ln_g, P.ssm_ln_b);
    __syncthreads();
    gemm17<256,1024,256,1024,0>(S->cur, P.in_proj_w, nullptr, S->big);   // xz
    __syncthreads();
    // conv (degenerate, per-channel) + silu on xm = big[:, :512]
    for (int t = tid; t < 17*512; t += NT) {
        int l = t >> 9, d = t & 511;
        float v = fmaf(S->big[l*1024+d], __ldg(P.conv_w+d), __ldg(P.conv_b+d));
        S->big[l*1024+d] = silu_f(v);
    }
    __syncthreads();
    // dbl = xm @ x_proj_w  (17 x 24)
    for (int t = tid; t < 408; t += NT) {
        int l = t/24, n = t - l*24;
        const float* xr = S->big + l*1024;
        float a = 0.f;
#pragma unroll 4
        for (int k = 0; k < 512; ++k) a = fmaf(xr[k], __ldg(P.x_proj_w + k*24 + n), a);
        S->dbl[t] = a;
    }
    __syncthreads();
    // selective scan: each thread owns channels d0=tid, d1=tid+256; state in regs
    {
        const int d0 = tid, d1 = tid + 256;
        float negA0[4], negA1[4], h0[4] = {0,0,0,0}, h1[4] = {0,0,0,0};
        float wdt0[16], wdt1[16];
#pragma unroll
        for (int s = 0; s < 4; ++s) {
            negA0[s] = -expf(__ldg(P.A_log + d0*4 + s));
            negA1[s] = -expf(__ldg(P.A_log + d1*4 + s));
        }
#pragma unroll
        for (int r = 0; r < 16; ++r) {
            wdt0[r] = __ldg(P.dt_proj_w + r*512 + d0);
            wdt1[r] = __ldg(P.dt_proj_w + r*512 + d1);
        }
        const float dpb0 = __ldg(P.dt_proj_b + d0), dpb1 = __ldg(P.dt_proj_b + d1);
        const float Dp0  = __ldg(P.Dp + d0),        Dp1  = __ldg(P.Dp + d1);
#pragma unroll 1
        for (int l = 0; l < 17; ++l) {
            const float* dl = S->dbl + l*24;
            float t0 = dpb0, t1 = dpb1;
#pragma unroll
            for (int r = 0; r < 16; ++r) { float dv = dl[r]; t0 = fmaf(dv, wdt0[r], t0); t1 = fmaf(dv, wdt1[r], t1); }
            const float dt0 = softplus_f(t0), dt1 = softplus_f(t1);
            const float xm0 = S->big[l*1024 + d0], xm1 = S->big[l*1024 + d1];
            float y0 = 0.f, y1 = 0.f;
#pragma unroll
            for (int s = 0; s < 4; ++s) {
                const float Bv = dl[16+s], Cv = dl[20+s];
                h0[s] = fmaf(expf(dt0*negA0[s]), h0[s], dt0*Bv*xm0);
                h1[s] = fmaf(expf(dt1*negA1[s]), h1[s], dt1*Bv*xm1);
                y0 = fmaf(h0[s], Cv, y0);
                y1 = fmaf(h1[s], Cv, y1);
            }
            y0 = fmaf(Dp0, xm0, y0);
            y1 = fmaf(Dp1, xm1, y1);
            const float z0 = S->big[l*1024 + 512 + d0], z1 = S->big[l*1024 + 512 + d1];
            S->b512[l*512 + d0] = y0 * silu_f(z0);
            S->b512[l*512 + d1] = y1 * silu_f(z1);
        }
    }
    __syncthreads();
    gemm17<512,256,512,256,0>(S->b512, P.out_proj_w, nullptr, S->big);   // xs_out -> tA
    __syncthreads();
    // x = 2*res1 + xs_out[GRAPH]  (becomes res2)
    for (int t = tid; t < 4352; t += NT) {
        int l = t >> 8, d = t & 255;
        S->res[t] = 2.f*S->res[t] + S->big[c_graph[l]*256 + d];
    }
    __syncthreads();

    // ================= Stage C: attention =================
    ln17(S->res, S->cur, P.ln1_g, P.ln1_b);
    __syncthreads();
    gemm17<256,768,256,1024,0>(S->cur, P.qkv_w, nullptr, S->big);        // q|k|v per row
    __syncthreads();
    {
        const int lane = tid & 31, w = tid >> 5;
        const float scale = 0.17677669529663687f;   // 32^-0.5
#pragma unroll 1
        for (int task = w; task < 136; task += 8) {
            const int q = task >> 3, h = task & 7;
            const int off = h*32 + lane;
            const float qj = S->big[q*1024 + off];
            float sc[17];
            float mx = -1e30f;
#pragma unroll
            for (int k = 0; k < 17; ++k) {
                float p = qj * S->big[k*1024 + 256 + off];
#pragma unroll
                for (int o = 16; o; o >>= 1) p += __shfl_xor_sync(0xffffffffu, p, o);
                p *= scale;
                sc[k] = p;
                mx = fmaxf(mx, p);
            }
            float sum = 0.f;
#pragma unroll
            for (int k = 0; k < 17; ++k) { sc[k] = expf(sc[k]-mx); sum += sc[k]; }
            const float inv = 1.f/sum;
            float acc = 0.f;
#pragma unroll
            for (int k = 0; k < 17; ++k)
                acc = fmaf(sc[k]*inv, S->big[k*1024 + 512 + off], acc);
            S->b512[q*256 + off] = acc;    // t_o
        }
    }
    __syncthreads();
    gemm17<256,256,256,256,0>(S->b512, P.attn_proj_w, P.attn_proj_b, S->cur);
    __syncthreads();
    for (int t = tid; t < 4352; t += NT) S->cur[t] += S->res[t];         // x1
    __syncthreads();

    // ================= Stage D: MLP =================
    ln17(S->cur, S->b512, P.ln2_g, P.ln2_b);                             // t_o = ln(x1)
    __syncthreads();
    gemm17<256,1024,256,1024,1>(S->b512, P.mlp_w1, P.mlp_b1, S->big);    // gelu
    __syncthreads();
    gemm17<1024,256,1024,256,0>(S->big, P.mlp_w2, P.mlp_b2, S->b512);    // m -> t_o
    __syncthreads();

    // out = x1 + m + res2
    {
        float* op = P.out + (size_t)b*4352;
        for (int t = tid; t < 4352; t += NT)
            op[t] = S->b512[t] + S->cur[t] + S->res[t];
    }
}

extern "C" void kernel_launch(void* const* d_in, const int* in_sizes, int n_in,
                              void* d_out, int out_size)
{
    Params P;
    P.x          = (const float*)d_in[0];
    P.gcn_ln_g   = (const float*)d_in[1];
    P.gcn_ln_b   = (const float*)d_in[2];
    P.gcn_w1     = (const float*)d_in[3];
    P.gcn_b1     = (const float*)d_in[4];
    P.gcn_w2     = (const float*)d_in[5];
    P.gcn_b2     = (const float*)d_in[6];
    P.bp         = (const float*)d_in[7];
    P.ssm_ln_g   = (const float*)d_in[8];
    P.ssm_ln_b   = (const float*)d_in[9];
    P.in_proj_w  = (const float*)d_in[10];
    P.conv_w     = (const float*)d_in[11];
    P.conv_b     = (const float*)d_in[12];
    P.x_proj_w   = (const float*)d_in[13];
    P.dt_proj_w  = (const float*)d_in[14];
    P.dt_proj_b  = (const float*)d_in[15];
    P.A_log      = (const float*)d_in[16];
    P.Dp         = (const float*)d_in[17];
    P.out_proj_w = (const float*)d_in[18];
    P.ln1_g      = (const float*)d_in[19];
    P.ln1_b      = (const float*)d_in[20];
    P.qkv_w      = (const float*)d_in[21];
    P.attn_proj_w= (const float*)d_in[22];
    P.attn_proj_b= (const float*)d_in[23];
    P.ln2_g      = (const float*)d_in[24];
    P.ln2_b      = (const float*)d_in[25];
    P.mlp_w1     = (const float*)d_in[26];
    P.mlp_b1     = (const float*)d_in[27];
    P.mlp_w2     = (const float*)d_in[28];
    P.mlp_b2     = (const float*)d_in[29];
    P.out        = (float*)d_out;
    P.nb         = in_sizes[0] / (17*256);

    const int smem = (int)sizeof(Smem);
    cudaFuncSetAttribute(block_kernel, cudaFuncAttributeMaxDynamicSharedMemorySize, smem);
    block_kernel<<<P.nb, NT, smem>>>(P);
}

// round 2
// speedup vs baseline: 1.2685x; 1.2685x over previous
#include <cuda_runtime.h>
#include <math.h>

#define NT 512

// ---- graph constants -------------------------------------------------------
__constant__ int   c_adj[17]  = {0x93,0x7,0xE,0xC,0x31,0x70,0x60,0x181,0x4B80,
                                 0x700,0x600,0x1900,0x3800,0x3000,0xC100,0x1C000,0x18000};
__constant__ float c_deg[17]  = {4,3,3,2,3,3,2,3,5,3,2,3,3,2,3,3,2};
__constant__ int   c_hop[17]  = {0,1,4,7,2,5,8,3,6,9,11,14,10,12,15,13,16};
__constant__ int   c_graph[17]= {0,1,4,7,2,5,8,3,6,9,12,10,13,15,11,14,16};
__constant__ int   c_bpe[17]  = {0,1,2,0,1,2,0,1,2,0,3,4,0,3,4,3,4};

struct Params {
    const float *x;
    const float *gcn_ln_g, *gcn_ln_b;
    const float *gcn_w1, *gcn_b1, *gcn_w2, *gcn_b2;
    const float *bp;
    const float *ssm_ln_g, *ssm_ln_b;
    const float *in_proj_w;
    const float *conv_w, *conv_b;
    const float *x_proj_w;
    const float *dt_proj_w, *dt_proj_b;
    const float *A_log, *Dp, *out_proj_w;
    const float *ln1_g, *ln1_b;
    const float *qkv_w, *attn_proj_w, *attn_proj_b;
    const float *ln2_g, *ln2_b;
    const float *mlp_w1, *mlp_b1, *mlp_w2, *mlp_b2;
    float *out;
    int nb;
};

struct Smem {
    float res[17*256];    // residual / evolving x
    float cur[17*256];    // working 256-wide buffer
    float big[17*1024];   // xz / qkv / mlp hidden
    float b512[17*512];   // gcn hidden / ssm y / t_o
    float dbl[17*24];
    float ahat[17*17];
};

__device__ __forceinline__ float gelu_t(float x) {
    float x3 = x*x*x;
    return 0.5f*x*(1.f + tanhf(0.7978845608028654f*(x + 0.044715f*x3)));
}
__device__ __forceinline__ float silu_f(float x) { return x / (1.f + expf(-x)); }
__device__ __forceinline__ float softplus_f(float x) { return x > 20.f ? x : log1pf(expf(x)); }

// out[17][OUTS(n<N)] = ACT( in[17][INS] @ W[K][N] + bias[N] )
// If N < NT (i.e. N==256), threads split rows: g0 -> rows 0..8, g1 -> rows 9..16.
template<int K, int N, int INS, int OUTS, int ACT>
__device__ __forceinline__ void gemm17(const float* __restrict__ in,
                                       const float* __restrict__ W,
                                       const float* __restrict__ bias,
                                       float* __restrict__ out)
{
    if constexpr (N >= NT) {
#pragma unroll 1
        for (int n0 = 0; n0 < N; n0 += NT) {
            const int n = n0 + threadIdx.x;
            if (n < N) {
                float acc[17];
                const float bv = bias ? __ldg(bias + n) : 0.f;
#pragma unroll
                for (int l = 0; l < 17; ++l) acc[l] = bv;
#pragma unroll 1
                for (int k = 0; k < K; k += 4) {
                    const float w0 = __ldg(W + (size_t)(k+0)*N + n);
                    const float w1 = __ldg(W + (size_t)(k+1)*N + n);
                    const float w2 = __ldg(W + (size_t)(k+2)*N + n);
                    const float w3 = __ldg(W + (size_t)(k+3)*N + n);
#pragma unroll
                    for (int l = 0; l < 17; ++l) {
                        const float4 iv = *reinterpret_cast<const float4*>(in + l*INS + k);
                        acc[l] = fmaf(iv.x, w0, acc[l]);
                        acc[l] = fmaf(iv.y, w1, acc[l]);
                        acc[l] = fmaf(iv.z, w2, acc[l]);
                        acc[l] = fmaf(iv.w, w3, acc[l]);
                    }
                }
#pragma unroll
                for (int l = 0; l < 17; ++l) {
                    float v = acc[l];
                    if (ACT == 1) v = gelu_t(v);
                    out[l*OUTS + n] = v;
                }
            }
        }
    } else {
        // N == 256 path: 2 groups over rows
        const int n = threadIdx.x & (N-1);
        const int g = threadIdx.x >> 8;           // 0 or 1
        const int lbeg = g ? 9 : 0;
        const int lcnt = g ? 8 : 9;
        float acc[9];
        const float bv = bias ? __ldg(bias + n) : 0.f;
#pragma unroll
        for (int li = 0; li < 9; ++li) acc[li] = bv;
        const float* inb = in + lbeg*INS;
#pragma unroll 1
        for (int k = 0; k < K; k += 4) {
            const float w0 = __ldg(W + (size_t)(k+0)*N + n);
            const float w1 = __ldg(W + (size_t)(k+1)*N + n);
            const float w2 = __ldg(W + (size_t)(k+2)*N + n);
            const float w3 = __ldg(W + (size_t)(k+3)*N + n);
#pragma unroll
            for (int li = 0; li < 9; ++li) {
                if (li < lcnt) {
                    const float4 iv = *reinterpret_cast<const float4*>(inb + li*INS + k);
                    acc[li] = fmaf(iv.x, w0, acc[li]);
                    acc[li] = fmaf(iv.y, w1, acc[li]);
                    acc[li] = fmaf(iv.z, w2, acc[li]);
                    acc[li] = fmaf(iv.w, w3, acc[li]);
                }
            }
        }
#pragma unroll
        for (int li = 0; li < 9; ++li) {
            if (li < lcnt) {
                float v = acc[li];
                if (ACT == 1) v = gelu_t(v);
                out[(lbeg+li)*OUTS + n] = v;
            }
        }
    }
}

// layernorm over last dim 256; src/dst stride 256 (warp per row)
__device__ __forceinline__ void ln17(const float* __restrict__ src, float* __restrict__ dst,
                                     const float* __restrict__ g, const float* __restrict__ b)
{
    const int w = threadIdx.x >> 5, lane = threadIdx.x & 31;
    for (int l = w; l < 17; l += NT/32) {
        const float* row = src + l*256;
        float s = 0.f;
#pragma unroll
        for (int i = 0; i < 8; ++i) s += row[lane + 32*i];
#pragma unroll
        for (int o = 16; o; o >>= 1) s += __shfl_xor_sync(0xffffffffu, s, o);
        const float m = s * (1.f/256.f);
        float v = 0.f;
#pragma unroll
        for (int i = 0; i < 8; ++i) { float d = row[lane+32*i]-m; v = fmaf(d,d,v); }
#pragma unroll
        for (int o = 16; o; o >>= 1) v += __shfl_xor_sync(0xffffffffu, v, o);
        const float r = rsqrtf(v*(1.f/256.f) + 1e-5f);
#pragma unroll
        for (int i = 0; i < 8; ++i) {
            int c = lane + 32*i;
            dst[l*256+c] = (row[c]-m)*r*__ldg(g+c) + __ldg(b+c);
        }
    }
}

// out[i][d] = sum_j ahat[i][j] * in[j][d]   (strides = D)
template<int D>
__device__ __forceinline__ void mix17(const float* __restrict__ in, float* __restrict__ out,
                                      const float* __restrict__ ah)
{
#pragma unroll 1
    for (int d0 = 0; d0 < D; d0 += NT) {
        const int d = d0 + threadIdx.x;
        if (d < D) {
            float v[17];
#pragma unroll
            for (int j = 0; j < 17; ++j) v[j] = in[j*D + d];
#pragma unroll 1
            for (int i = 0; i < 17; ++i) {
                float a = 0.f;
#pragma unroll
                for (int j = 0; j < 17; ++j) a = fmaf(ah[i*17+j], v[j], a);
                out[i*D + d] = a;
            }
        }
    }
}

__global__ void __launch_bounds__(NT, 1)
block_kernel(Params P)
{
    extern __shared__ float smraw[];
    Smem* S = reinterpret_cast<Smem*>(smraw);
    const int tid = threadIdx.x;
    const int b = blockIdx.x;
    if (b >= P.nb) return;

    // ---- load x -> res; build A_HAT ----
    {
        const float4* xin = reinterpret_cast<const float4*>(P.x + (size_t)b*4352);
        float4* rr = reinterpret_cast<float4*>(S->res);
        for (int i = tid; i < 1088; i += NT) rr[i] = xin[i];
        for (int t = tid; t < 289; t += NT) {
            int i = t/17, j = t - i*17;
            S->ahat[t] = ((c_adj[i]>>j)&1) ? rsqrtf(c_deg[i]*c_deg[j]) : 0.f;
        }
    }
    __syncthreads();

    // ================= Stage A: GCN =================
    ln17(S->res, S->cur, P.gcn_ln_g, P.gcn_ln_b);
    __syncthreads();
    mix17<256>(S->cur, S->big, S->ahat);                       // tA = big[17][256]
    __syncthreads();
    gemm17<256,512,256,512,1>(S->big, P.gcn_w1, P.gcn_b1, S->b512);  // gelu
    __syncthreads();
    mix17<512>(S->b512, S->big, S->ahat);                      // t5 = big[17][512]
    __syncthreads();
    gemm17<512,256,512,256,0>(S->big, P.gcn_w2, P.gcn_b2, S->cur);
    __syncthreads();
    for (int t = tid; t < 4352; t += NT) S->res[t] += S->cur[t];   // x = res + h  (res1)
    __syncthreads();

    // ================= Stage B: SSM (mamba) =================
    for (int t = tid; t < 4352; t += NT) {
        int l = t >> 8, d = t & 255;
        S->big[l*256 + d] = S->res[c_hop[l]*256 + d] + __ldg(P.bp + c_bpe[l]*256 + d);
    }
    __syncthreads();
    ln17(S->big, S->cur, P.ssm_ln_g, P.ssm_ln_b);
    __syncthreads();
    gemm17<256,1024,256,1024,0>(S->cur, P.in_proj_w, nullptr, S->big);   // xz
    __syncthreads();
    // conv (degenerate per-channel) + silu on xm = big[:, :512]
    for (int t = tid; t < 17*512; t += NT) {
        int l = t >> 9, d = t & 511;
        float v = fmaf(S->big[l*1024+d], __ldg(P.conv_w+d), __ldg(P.conv_b+d));
        S->big[l*1024+d] = silu_f(v);
    }
    __syncthreads();
    // dbl = xm @ x_proj_w  (17 x 24)
    for (int t = tid; t < 408; t += NT) {
        int l = t/24, n = t - l*24;
        const float* xr = S->big + l*1024;
        float a = 0.f;
#pragma unroll 4
        for (int k = 0; k < 512; ++k) a = fmaf(xr[k], __ldg(P.x_proj_w + k*24 + n), a);
        S->dbl[t] = a;
    }
    __syncthreads();
    // selective scan: each thread owns channel d = tid; state in regs
    {
        const int d = tid;
        float negA[4], h[4] = {0,0,0,0};
        float wdt[16];
#pragma unroll
        for (int s = 0; s < 4; ++s) negA[s] = -expf(__ldg(P.A_log + d*4 + s));
#pragma unroll
        for (int r = 0; r < 16; ++r) wdt[r] = __ldg(P.dt_proj_w + r*512 + d);
        const float dpb = __ldg(P.dt_proj_b + d);
        const float Dp  = __ldg(P.Dp + d);
#pragma unroll 1
        for (int l = 0; l < 17; ++l) {
            const float* dl = S->dbl + l*24;
            float t0 = dpb;
#pragma unroll
            for (int r = 0; r < 16; ++r) t0 = fmaf(dl[r], wdt[r], t0);
            const float dt = softplus_f(t0);
            const float xm = S->big[l*1024 + d];
            float y = 0.f;
#pragma unroll
            for (int s = 0; s < 4; ++s) {
                const float Bv = dl[16+s], Cv = dl[20+s];
                h[s] = fmaf(expf(dt*negA[s]), h[s], dt*Bv*xm);
                y = fmaf(h[s], Cv, y);
            }
            y = fmaf(Dp, xm, y);
            const float z = S->big[l*1024 + 512 + d];
            S->b512[l*512 + d] = y * silu_f(z);
        }
    }
    __syncthreads();
    gemm17<512,256,512,256,0>(S->b512, P.out_proj_w, nullptr, S->big);   // xs_out (stride 256)
    __syncthreads();
    for (int t = tid; t < 4352; t += NT) {
        int l = t >> 8, d = t & 255;
        S->res[t] = 2.f*S->res[t] + S->big[c_graph[l]*256 + d];           // res2
    }
    __syncthreads();

    // ================= Stage C: attention =================
    ln17(S->res, S->cur, P.ln1_g, P.ln1_b);
    __syncthreads();
    gemm17<256,768,256,1024,0>(S->cur, P.qkv_w, nullptr, S->big);        // q|k|v per row
    __syncthreads();
    {
        const int lane = tid & 31, w = tid >> 5;
        const float scale = 0.17677669529663687f;   // 32^-0.5
#pragma unroll 1
        for (int task = w; task < 136; task += NT/32) {
            const int q = task >> 3, h = task & 7;
            const int off = h*32 + lane;
            const float qj = S->big[q*1024 + off];
            float sc[17];
            float mx = -1e30f;
#pragma unroll
            for (int k = 0; k < 17; ++k) {
                float p = qj * S->big[k*1024 + 256 + off];
#pragma unroll
                for (int o = 16; o; o >>= 1) p += __shfl_xor_sync(0xffffffffu, p, o);
                p *= scale;
                sc[k] = p;
                mx = fmaxf(mx, p);
            }
            float sum = 0.f;
#pragma unroll
            for (int k = 0; k < 17; ++k) { sc[k] = expf(sc[k]-mx); sum += sc[k]; }
            const float inv = 1.f/sum;
            float acc = 0.f;
#pragma unroll
            for (int k = 0; k < 17; ++k)
                acc = fmaf(sc[k]*inv, S->big[k*1024 + 512 + off], acc);
            S->b512[q*256 + off] = acc;    // t_o
        }
    }
    __syncthreads();
    gemm17<256,256,256,256,0>(S->b512, P.attn_proj_w, P.attn_proj_b, S->cur);
    __syncthreads();
    for (int t = tid; t < 4352; t += NT) S->cur[t] += S->res[t];         // x1
    __syncthreads();

    // ================= Stage D: MLP =================
    ln17(S->cur, S->b512, P.ln2_g, P.ln2_b);                             // t_o = ln(x1)
    __syncthreads();
    gemm17<256,1024,256,1024,1>(S->b512, P.mlp_w1, P.mlp_b1, S->big);    // gelu
    __syncthreads();
    gemm17<1024,256,1024,256,0>(S->big, P.mlp_w2, P.mlp_b2, S->b512);    // m -> t_o
    __syncthreads();

    // out = x1 + m + res2
    {
        float* op = P.out + (size_t)b*4352;
        for (int t = tid; t < 4352; t += NT)
            op[t] = S->b512[t] + S->cur[t] + S->res[t];
    }
}

extern "C" void kernel_launch(void* const* d_in, const int* in_sizes, int n_in,
                              void* d_out, int out_size)
{
    Params P;
    P.x          = (const float*)d_in[0];
    P.gcn_ln_g   = (const float*)d_in[1];
    P.gcn_ln_b   = (const float*)d_in[2];
    P.gcn_w1     = (const float*)d_in[3];
    P.gcn_b1     = (const float*)d_in[4];
    P.gcn_w2     = (const float*)d_in[5];
    P.gcn_b2     = (const float*)d_in[6];
    P.bp         = (const float*)d_in[7];
    P.ssm_ln_g   = (const float*)d_in[8];
    P.ssm_ln_b   = (const float*)d_in[9];
    P.in_proj_w  = (const float*)d_in[10];
    P.conv_w     = (const float*)d_in[11];
    P.conv_b     = (const float*)d_in[12];
    P.x_proj_w   = (const float*)d_in[13];
    P.dt_proj_w  = (const float*)d_in[14];
    P.dt_proj_b  = (const float*)d_in[15];
    P.A_log      = (const float*)d_in[16];
    P.Dp         = (const float*)d_in[17];
    P.out_proj_w = (const float*)d_in[18];
    P.ln1_g      = (const float*)d_in[19];
    P.ln1_b      = (const float*)d_in[20];
    P.qkv_w      = (const float*)d_in[21];
    P.attn_proj_w= (const float*)d_in[22];
    P.attn_proj_b= (const float*)d_in[23];
    P.ln2_g      = (const float*)d_in[24];
    P.ln2_b      = (const float*)d_in[25];
    P.mlp_w1     = (const float*)d_in[26];
    P.mlp_b1     = (const float*)d_in[27];
    P.mlp_w2     = (const float*)d_in[28];
    P.mlp_b2     = (const float*)d_in[29];
    P.out        = (float*)d_out;
    P.nb         = in_sizes[0] / (17*256);

    const int smem = (int)sizeof(Smem);
    cudaFuncSetAttribute(block_kernel, cudaFuncAttributeMaxDynamicSharedMemorySize, smem);
    block_kernel<<<P.nb, NT, smem>>>(P);
}

// round 4
// speedup vs baseline: 3.4036x; 2.6831x over previous
#include <cuda_runtime.h>
#include <cuda_bf16.h>
#include <cstdint>
#include <math.h>

#define TMAX 69632

__constant__ int   c_adj[17]  = {0x93,0x7,0xE,0xC,0x31,0x70,0x60,0x181,0x4B80,
                                 0x700,0x600,0x1900,0x3800,0x3000,0xC100,0x1C000,0x18000};
__constant__ float c_deg[17]  = {4,3,3,2,3,3,2,3,5,3,2,3,3,2,3,3,2};
__constant__ int   c_hop[17]  = {0,1,4,7,2,5,8,3,6,9,11,14,10,12,15,13,16};
__constant__ int   c_graph[17]= {0,1,4,7,2,5,8,3,6,9,12,10,13,15,11,14,16};
__constant__ int   c_bpe[17]  = {0,1,2,0,1,2,0,1,2,0,3,4,0,3,4,3,4};

__device__ __nv_bfloat16 g_bufA[(size_t)TMAX*1024];
__device__ __nv_bfloat16 g_bufB[(size_t)TMAX*768];
__device__ __nv_bfloat16 g_bufC[(size_t)TMAX*512];
__device__ __nv_bfloat16 g_bufD[(size_t)TMAX*256];
__device__ float g_res1[(size_t)TMAX*256];
__device__ float g_res2[(size_t)TMAX*256];
__device__ float g_x1  [(size_t)TMAX*256];
__device__ float g_tmpf[(size_t)TMAX*256];

__device__ __forceinline__ float gelu_t(float x) {
    float x3 = x*x*x;
    return 0.5f*x*(1.f + tanhf(0.7978845608028654f*(x + 0.044715f*x3)));
}
__device__ __forceinline__ float silu_f(float x) { return x / (1.f + expf(-x)); }
__device__ __forceinline__ float softplus_f(float x) { return x > 20.f ? x : log1pf(expf(x)); }

struct GP {
    const __nv_bfloat16* A;
    const float* W;
    const float* bias;
    const float* add1;
    const float* add2;
    const float* cw;
    const float* cb;
    float* outf;
    __nv_bfloat16* outh;
};

__device__ __forceinline__ void mma_bf16(float* d, const uint32_t* a,
                                         uint32_t b0, uint32_t b1)
{
    asm volatile(
        "mma.sync.aligned.m16n8k16.row.col.f32.bf16.bf16.f32 "
        "{%0,%1,%2,%3}, {%4,%5,%6,%7}, {%8,%9}, {%0,%1,%2,%3};\n"
        : "+f"(d[0]), "+f"(d[1]), "+f"(d[2]), "+f"(d[3])
        : "r"(a[0]), "r"(a[1]), "r"(a[2]), "r"(a[3]), "r"(b0), "r"(b1));
}

template<int N, int EPI>
__device__ __forceinline__ void epi_store(const GP& p, int t, int c,
                                          float v0, float v1, int Ttot)
{
    if (t >= Ttot) return;
    if (EPI == 0) {
        p.outh[(size_t)t*N + c]   = __float2bfloat16(v0);
        p.outh[(size_t)t*N + c+1] = __float2bfloat16(v1);
    }
    if (EPI == 1) {
        v0 = gelu_t(v0 + __ldg(p.bias + c));
        v1 = gelu_t(v1 + __ldg(p.bias + c+1));
        p.outh[(size_t)t*N + c]   = __float2bfloat16(v0);
        p.outh[(size_t)t*N + c+1] = __float2bfloat16(v1);
    }
    if (EPI == 2) {
        p.outf[(size_t)t*256 + c]   = v0 + __ldg(p.bias + c)   + p.add1[(size_t)t*256 + c];
        p.outf[(size_t)t*256 + c+1] = v1 + __ldg(p.bias + c+1) + p.add1[(size_t)t*256 + c+1];
    }
    if (EPI == 3) {
        p.outf[(size_t)t*256 + c]   = v0;
        p.outf[(size_t)t*256 + c+1] = v1;
    }
    if (EPI == 4) {
        if (c < 512) {
            v0 = silu_f(fmaf(v0, __ldg(p.cw + c),   __ldg(p.cb + c)));
            v1 = silu_f(fmaf(v1, __ldg(p.cw + c+1), __ldg(p.cb + c+1)));
        } else {
            v0 = silu_f(v0);
            v1 = silu_f(v1);
        }
        p.outh[(size_t)t*1024 + c]   = __float2bfloat16(v0);
        p.outh[(size_t)t*1024 + c+1] = __float2bfloat16(v1);
    }
    if (EPI == 5) {
        p.outf[(size_t)t*256 + c]   = v0 + __ldg(p.bias + c)
                                         + p.add1[(size_t)t*256 + c] + p.add2[(size_t)t*256 + c];
        p.outf[(size_t)t*256 + c+1] = v1 + __ldg(p.bias + c+1)
                                         + p.add1[(size_t)t*256 + c+1] + p.add2[(size_t)t*256 + c+1];
    }
}

template<int K, int N, int EPI>
__global__ void __launch_bounds__(256) gemm_tc(GP p, int Ttot)
{
    __shared__ __nv_bfloat16 As[128][34];
    __shared__ __nv_bfloat16 Bs[128][34];
    const int tid  = threadIdx.x;
    const int lane = tid & 31;
    const int wid  = tid >> 5;
    const int wm = wid & 3;
    const int wn = wid >> 2;
    const int mBase = blockIdx.y * 128;
    const int nBase = blockIdx.x * 128;
    const int g  = lane >> 2;
    const int tq = lane & 3;

    float acc[2][8][4];
    for (int a = 0; a < 2; ++a)
        for (int b = 0; b < 8; ++b)
            for (int c = 0; c < 4; ++c)
                acc[a][b][c] = 0.f;

    for (int kt = 0; kt < K; kt += 32) {
        {
            const int r  = tid >> 1;
            const int hc = (tid & 1) * 16;
            const int gr = mBase + r;
            uint4 v0 = make_uint4(0u,0u,0u,0u);
            uint4 v1 = make_uint4(0u,0u,0u,0u);
            if (gr < Ttot) {
                const uint4* src = reinterpret_cast<const uint4*>(p.A + (size_t)gr*K + kt + hc);
                v0 = src[0];
                v1 = src[1];
            }
            uint32_t u[8];
            u[0]=v0.x; u[1]=v0.y; u[2]=v0.z; u[3]=v0.w;
            u[4]=v1.x; u[5]=v1.y; u[6]=v1.z; u[7]=v1.w;
            for (int j = 0; j < 8; ++j)
                *reinterpret_cast<uint32_t*>(&As[r][hc + 2*j]) = u[j];
        }
        {
            const int kr = tid >> 3;
            const int nq = (tid & 7) * 16;
            const float* wrow = p.W + (size_t)(kt + kr)*N + nBase + nq;
            for (int i = 0; i < 4; ++i) {
                float4 f = __ldg(reinterpret_cast<const float4*>(wrow) + i);
                Bs[nq + 4*i + 0][kr] = __float2bfloat16(f.x);
                Bs[nq + 4*i + 1][kr] = __float2bfloat16(f.y);
                Bs[nq + 4*i + 2][kr] = __float2bfloat16(f.z);
                Bs[nq + 4*i + 3][kr] = __float2bfloat16(f.w);
            }
        }
        __syncthreads();

        for (int ks = 0; ks < 32; ks += 16) {
            const int cp = 2*tq + ks;
            uint32_t afr[2][4];
            for (int mi = 0; mi < 2; ++mi) {
                const int row = wm*32 + mi*16 + g;
                afr[mi][0] = *reinterpret_cast<const uint32_t*>(&As[row  ][cp  ]);
                afr[mi][1] = *reinterpret_cast<const uint32_t*>(&As[row+8][cp  ]);
                afr[mi][2] = *reinterpret_cast<const uint32_t*>(&As[row  ][cp+8]);
                afr[mi][3] = *reinterpret_cast<const uint32_t*>(&As[row+8][cp+8]);
            }
            for (int ni = 0; ni < 8; ++ni) {
                const int nc = wn*64 + ni*8 + g;
                uint32_t b0 = *reinterpret_cast<const uint32_t*>(&Bs[nc][cp  ]);
                uint32_t b1 = *reinterpret_cast<const uint32_t*>(&Bs[nc][cp+8]);
                mma_bf16(acc[0][ni], afr[0], b0, b1);
                mma_bf16(acc[1][ni], afr[1], b0, b1);
            }
        }
        __syncthreads();
    }

    for (int mi = 0; mi < 2; ++mi) {
        const int r0 = mBase + wm*32 + mi*16 + g;
        for (int ni = 0; ni < 8; ++ni) {
            const int c0 = nBase + wn*64 + ni*8 + 2*tq;
            epi_store<N,EPI>(p, r0,   c0, acc[mi][ni][0], acc[mi][ni][1], Ttot);
            epi_store<N,EPI>(p, r0+8, c0, acc[mi][ni][2], acc[mi][ni][3], Ttot);
        }
    }
}

// ============================================================================
__device__ __forceinline__ void build_ahat(float* ah, int tid, int nthr)
{
    for (int t = tid; t < 289; t += nthr) {
        int i = t/17;
        int j = t - i*17;
        ah[t] = ((c_adj[i]>>j)&1) ? rsqrtf(c_deg[i]*c_deg[j]) : 0.f;
    }
}

__device__ __forceinline__ void ln_rows_f32(const float* src, float* dst,
                                            const float* g, const float* b, int nthr)
{
    const int w = threadIdx.x >> 5;
    const int lane = threadIdx.x & 31;
    for (int l = w; l < 17; l += nthr/32) {
        const float* row = src + l*256;
        float s = 0.f;
        for (int i = 0; i < 8; ++i) s += row[lane + 32*i];
        for (int o = 16; o; o >>= 1) s += __shfl_xor_sync(0xffffffffu, s, o);
        const float m = s * (1.f/256.f);
        float v = 0.f;
        for (int i = 0; i < 8; ++i) { float d = row[lane+32*i]-m; v = fmaf(d,d,v); }
        for (int o = 16; o; o >>= 1) v += __shfl_xor_sync(0xffffffffu, v, o);
        const float r = rsqrtf(v*(1.f/256.f) + 1e-5f);
        for (int i = 0; i < 8; ++i) {
            int c = lane + 32*i;
            dst[l*256+c] = (row[c]-m)*r*__ldg(g+c) + __ldg(b+c);
        }
    }
}

__device__ __forceinline__ void ln_rows_bf16(const float* src, __nv_bfloat16* dst,
                                             const float* g, const float* b, int nthr)
{
    const int w = threadIdx.x >> 5;
    const int lane = threadIdx.x & 31;
    for (int l = w; l < 17; l += nthr/32) {
        const float* row = src + l*256;
        float s = 0.f;
        for (int i = 0; i < 8; ++i) s += row[lane + 32*i];
        for (int o = 16; o; o >>= 1) s += __shfl_xor_sync(0xffffffffu, s, o);
        const float m = s * (1.f/256.f);
        float v = 0.f;
        for (int i = 0; i < 8; ++i) { float d = row[lane+32*i]-m; v = fmaf(d,d,v); }
        for (int o = 16; o; o >>= 1) v += __shfl_xor_sync(0xffffffffu, v, o);
        const float r = rsqrtf(v*(1.f/256.f) + 1e-5f);
        for (int i = 0; i < 8; ++i) {
            int c = lane + 32*i;
            dst[(size_t)l*256+c] = __float2bfloat16((row[c]-m)*r*__ldg(g+c) + __ldg(b+c));
        }
    }
}

__global__ void __launch_bounds__(256) k_pre(const float* x, const float* g, const float* bv)
{
    __shared__ float xs[17*256];
    __shared__ float cur[17*256];
    __shared__ float ah[289];
    const int b = blockIdx.x;
    const int tid = threadIdx.x;
    const float4* xp = reinterpret_cast<const float4*>(x + (size_t)b*4352);
    for (int i = tid; i < 1088; i += 256) reinterpret_cast<float4*>(xs)[i] = xp[i];
    build_ahat(ah, tid, 256);
    __syncthreads();
    ln_rows_f32(xs, cur, g, bv, 256);
    __syncthreads();
    const int d = tid;
    float v[17];
    for (int j = 0; j < 17; ++j) v[j] = cur[j*256 + d];
    for (int i = 0; i < 17; ++i) {
        float a = 0.f;
        for (int j = 0; j < 17; ++j) a = fmaf(ah[i*17+j], v[j], a);
        g_bufD[((size_t)b*17 + i)*256 + d] = __float2bfloat16(a);
    }
}

__global__ void __launch_bounds__(256) k_mid1()
{
    __shared__ float h[17*512];
    __shared__ float ah[289];
    const int b = blockIdx.x;
    const int tid = threadIdx.x;
    const __nv_bfloat16* ip = g_bufC + (size_t)b*8704;
    for (int i = tid; i < 8704; i += 256) h[i] = __bfloat162float(ip[i]);
    build_ahat(ah, tid, 256);
    __syncthreads();
    for (int half = 0; half < 2; ++half) {
        const int d = tid + half*256;
        float v[17];
        for (int j = 0; j < 17; ++j) v[j] = h[j*512 + d];
        for (int i = 0; i < 17; ++i) {
            float a = 0.f;
            for (int j = 0; j < 17; ++j) a = fmaf(ah[i*17+j], v[j], a);
            g_bufB[(size_t)b*8704 + (size_t)i*512 + d] = __float2bfloat16(a);
        }
    }
}

__global__ void __launch_bounds__(256) k_mid2(const float* bp, const float* g, const float* bv)
{
    __shared__ float xs[17*256];
    const int b = blockIdx.x;
    const int tid = threadIdx.x;
    for (int i = tid; i < 4352; i += 256) {
        int l = i >> 8;
        int d = i & 255;
        xs[i] = g_res1[(size_t)b*4352 + c_hop[l]*256 + d] + __ldg(bp + c_bpe[l]*256 + d);
    }
    __syncthreads();
    ln_rows_bf16(xs, g_bufD + (size_t)b*4352, g, bv, 256);
}

__global__ void __launch_bounds__(256) k_mid3(const float* g, const float* bv)
{
    __shared__ float r2[17*256];
    const int b = blockIdx.x;
    const int tid = threadIdx.x;
    for (int i = tid; i < 4352; i += 256) {
        int l = i >> 8;
        int d = i & 255;
        float v = 2.f*g_res1[(size_t)b*4352 + i] + g_tmpf[(size_t)b*4352 + c_graph[l]*256 + d];
        r2[i] = v;
        g_res2[(size_t)b*4352 + i] = v;
    }
    __syncthreads();
    ln_rows_bf16(r2, g_bufD + (size_t)b*4352, g, bv, 256);
}

__global__ void __launch_bounds__(256) k_ln2(const float* g, const float* bv)
{
    __shared__ float xs[17*256];
    const int b = blockIdx.x;
    const int tid = threadIdx.x;
    const float4* xp = reinterpret_cast<const float4*>(g_x1 + (size_t)b*4352);
    for (int i = tid; i < 1088; i += 256) reinterpret_cast<float4*>(xs)[i] = xp[i];
    __syncthreads();
    ln_rows_bf16(xs, g_bufD + (size_t)b*4352, g, bv, 256);
}

__global__ void __launch_bounds__(512) k_scan(const float* x_proj_w,
                                              const float* dt_proj_w,
                                              const float* dt_proj_b,
                                              const float* A_log,
                                              const float* Dpv)
{
    extern __shared__ float sm[];
    float* xm  = sm;
    float* zs  = sm + 8704;
    float* dbl = sm + 17408;
    const int b = blockIdx.x;
    const int tid = threadIdx.x;
    for (int i = tid; i < 8704; i += 512) {
        int l = i >> 9;
        int d = i & 511;
        const __nv_bfloat16* base = g_bufA + ((size_t)b*17 + l)*1024;
        xm[i] = __bfloat162float(base[d]);
        zs[i] = __bfloat162float(base[512 + d]);
    }
    __syncthreads();
    if (tid < 408) {
        int l = tid/24;
        int n = tid - l*24;
        const float* xr = xm + l*512;
        float a = 0.f;
        for (int k = 0; k < 512; ++k) a = fmaf(xr[k], __ldg(x_proj_w + k*24 + n), a);
        dbl[tid] = a;
    }
    __syncthreads();
    const int d = tid;
    float negA[4];
    float h[4] = {0.f,0.f,0.f,0.f};
    float wdt[16];
    for (int s = 0; s < 4; ++s) negA[s] = -expf(__ldg(A_log + d*4 + s));
    for (int r = 0; r < 16; ++r) wdt[r] = __ldg(dt_proj_w + r*512 + d);
    const float dpb = __ldg(dt_proj_b + d);
    const float Dp  = __ldg(Dpv + d);
    for (int l = 0; l < 17; ++l) {
        const float* dl = dbl + l*24;
        float t0 = dpb;
        for (int r = 0; r < 16; ++r) t0 = fmaf(dl[r], wdt[r], t0);
        const float dt = softplus_f(t0);
        const float xv = xm[l*512 + d];
        float y = 0.f;
        for (int s = 0; s < 4; ++s) {
            const float Bv = dl[16+s];
            const float Cv = dl[20+s];
            h[s] = fmaf(expf(dt*negA[s]), h[s], dt*Bv*xv);
            y = fmaf(h[s], Cv, y);
        }
        y = fmaf(Dp, xv, y);
        g_bufC[((size_t)b*17 + l)*512 + d] = __float2bfloat16(y * zs[l*512 + d]);
    }
}

__global__ void __launch_bounds__(512) k_attn()
{
    extern __shared__ float s[];
    const int b = blockIdx.x;
    const int tid = threadIdx.x;
    const __nv_bfloat16* qp = g_bufB + (size_t)b*13056;
    for (int i = tid; i < 13056; i += 512) s[i] = __bfloat162float(qp[i]);
    __syncthreads();
    const int lane = tid & 31;
    const int w = tid >> 5;
    const float scale = 0.17677669529663687f;
    for (int task = w; task < 136; task += 16) {
        const int q = task >> 3;
        const int hh = task & 7;
        const int off = hh*32 + lane;
        const float qj = s[q*768 + off];
        float sc[17];
        float mx = -1e30f;
        for (int k = 0; k < 17; ++k) {
            float pv = qj * s[k*768 + 256 + off];
            for (int o = 16; o; o >>= 1) pv += __shfl_xor_sync(0xffffffffu, pv, o);
            pv *= scale;
            sc[k] = pv;
            mx = fmaxf(mx, pv);
        }
        float sum = 0.f;
        for (int k = 0; k < 17; ++k) { sc[k] = expf(sc[k]-mx); sum += sc[k]; }
        const float inv = 1.f/sum;
        float acc = 0.f;
        for (int k = 0; k < 17; ++k)
            acc = fmaf(sc[k]*inv, s[k*768 + 512 + off], acc);
        g_bufD[((size_t)b*17 + q)*256 + off] = __float2bfloat16(acc);
    }
}

// ============================================================================
extern "C" void kernel_launch(void* const* d_in, const int* in_sizes, int n_in,
                              void* d_out, int out_size)
{
    const float *x          = (const float*)d_in[0];
    const float *gcn_ln_g   = (const float*)d_in[1];
    const float *gcn_ln_b   = (const float*)d_in[2];
    const float *gcn_w1     = (const float*)d_in[3];
    const float *gcn_b1     = (const float*)d_in[4];
    const float *gcn_w2     = (const float*)d_in[5];
    const float *gcn_b2     = (const float*)d_in[6];
    const float *bp         = (const float*)d_in[7];
    const float *ssm_ln_g   = (const float*)d_in[8];
    const float *ssm_ln_b   = (const float*)d_in[9];
    const float *in_proj_w  = (const float*)d_in[10];
    const float *conv_w     = (const float*)d_in[11];
    const float *conv_b     = (const float*)d_in[12];
    const float *x_proj_w   = (const float*)d_in[13];
    const float *dt_proj_w  = (const float*)d_in[14];
    const float *dt_proj_b  = (const float*)d_in[15];
    const float *A_log      = (const float*)d_in[16];
    const float *Dp         = (const float*)d_in[17];
    const float *out_proj_w = (const float*)d_in[18];
    const float *ln1_g      = (const float*)d_in[19];
    const float *ln1_b      = (const float*)d_in[20];
    const float *qkv_w      = (const float*)d_in[21];
    const float *attn_proj_w= (const float*)d_in[22];
    const float *attn_proj_b= (const float*)d_in[23];
    const float *ln2_g      = (const float*)d_in[24];
    const float *ln2_b      = (const float*)d_in[25];
    const float *mlp_w1     = (const float*)d_in[26];
    const float *mlp_b1     = (const float*)d_in[27];
    const float *mlp_w2     = (const float*)d_in[28];
    const float *mlp_b2     = (const float*)d_in[29];
    float* outp             = (float*)d_out;

    const int nb   = in_sizes[0] / 4352;
    const int Ttot = nb * 17;
    const int mT   = (Ttot + 127) / 128;

    __nv_bfloat16 *bufA = 0, *bufB = 0, *bufC = 0, *bufD = 0;
    float *res1 = 0, *res2 = 0, *x1 = 0, *tmpf = 0;
    cudaGetSymbolAddress((void**)&bufA, g_bufA);
    cudaGetSymbolAddress((void**)&bufB, g_bufB);
    cudaGetSymbolAddress((void**)&bufC, g_bufC);
    cudaGetSymbolAddress((void**)&bufD, g_bufD);
    cudaGetSymbolAddress((void**)&res1, g_res1);
    cudaGetSymbolAddress((void**)&res2, g_res2);
    cudaGetSymbolAddress((void**)&x1,   g_x1);
    cudaGetSymbolAddress((void**)&tmpf, g_tmpf);

    cudaFuncSetAttribute(k_scan, cudaFuncAttributeMaxDynamicSharedMemorySize, 17816*4);
    cudaFuncSetAttribute(k_attn, cudaFuncAttributeMaxDynamicSharedMemorySize, 13056*4);

    // Stage A: GCN
    k_pre<<<nb, 256>>>(x, gcn_ln_g, gcn_ln_b);
    GP p1 = { bufD, gcn_w1, gcn_b1, 0, 0, 0, 0, 0, bufC };
    gemm_tc<256,512,1><<<dim3(4, mT), 256>>>(p1, Ttot);
    k_mid1<<<nb, 256>>>();
    GP p2 = { bufB, gcn_w2, gcn_b2, x, 0, 0, 0, res1, 0 };
    gemm_tc<512,256,2><<<dim3(2, mT), 256>>>(p2, Ttot);

    // Stage B: SSM
    k_mid2<<<nb, 256>>>(bp, ssm_ln_g, ssm_ln_b);
    GP p3 = { bufD, in_proj_w, 0, 0, 0, conv_w, conv_b, 0, bufA };
    gemm_tc<256,1024,4><<<dim3(8, mT), 256>>>(p3, Ttot);
    k_scan<<<nb, 512, 17816*4>>>(x_proj_w, dt_proj_w, dt_proj_b, A_log, Dp);
    GP p4 = { bufC, out_proj_w, 0, 0, 0, 0, 0, tmpf, 0 };
    gemm_tc<512,256,3><<<dim3(2, mT), 256>>>(p4, Ttot);
    k_mid3<<<nb, 256>>>(ln1_g, ln1_b);

    // Stage C: attention
    GP p5 = { bufD, qkv_w, 0, 0, 0, 0, 0, 0, bufB };
    gemm_tc<256,768,0><<<dim3(6, mT), 256>>>(p5, Ttot);
    k_attn<<<nb, 512, 13056*4>>>();
    GP p6 = { bufD, attn_proj_w, attn_proj_b, res2, 0, 0, 0, x1, 0 };
    gemm_tc<256,256,2><<<dim3(2, mT), 256>>>(p6, Ttot);

    // Stage D: MLP
    k_ln2<<<nb, 256>>>(ln2_g, ln2_b);
    GP p7 = { bufD, mlp_w1, mlp_b1, 0, 0, 0, 0, 0, bufA };
    gemm_tc<256,1024,1><<<dim3(8, mT), 256>>>(p7, Ttot);
    GP p8 = { bufA, mlp_w2, mlp_b2, x1, res2, 0, 0, outp, 0 };
    gemm_tc<1024,256,5><<<dim3(2, mT), 256>>>(p8, Ttot);
}

// round 5
// speedup vs baseline: 4.1618x; 1.2228x over previous
#include <cuda_runtime.h>
#include <cuda_bf16.h>
#include <cstdint>
#include <math.h>

#define TMAX 69632

__constant__ int   c_adj[17]  = {0x93,0x7,0xE,0xC,0x31,0x70,0x60,0x181,0x4B80,
                                 0x700,0x600,0x1900,0x3800,0x3000,0xC100,0x1C000,0x18000};
__constant__ float c_deg[17]  = {4,3,3,2,3,3,2,3,5,3,2,3,3,2,3,3,2};
__constant__ int   c_hop[17]  = {0,1,4,7,2,5,8,3,6,9,11,14,10,12,15,13,16};
__constant__ int   c_graph[17]= {0,1,4,7,2,5,8,3,6,9,12,10,13,15,11,14,16};
__constant__ int   c_bpe[17]  = {0,1,2,0,1,2,0,1,2,0,3,4,0,3,4,3,4};

__device__ __nv_bfloat16 g_bufA[(size_t)TMAX*1024];
__device__ __nv_bfloat16 g_bufB[(size_t)TMAX*768];
__device__ __nv_bfloat16 g_bufC[(size_t)TMAX*512];
__device__ __nv_bfloat16 g_bufD[(size_t)TMAX*256];
__device__ float g_res1[(size_t)TMAX*256];
__device__ float g_res2[(size_t)TMAX*256];
__device__ float g_x1  [(size_t)TMAX*256];
__device__ float g_tmpf[(size_t)TMAX*256];
__device__ __nv_bfloat16 g_wt[1441792];   // all transposed bf16 weights

__device__ __forceinline__ float gelu_t(float x) {
    float x3 = x*x*x;
    return 0.5f*x*(1.f + tanhf(0.7978845608028654f*(x + 0.044715f*x3)));
}
__device__ __forceinline__ float silu_f(float x) { return x / (1.f + expf(-x)); }
__device__ __forceinline__ float softplus_f(float x) { return x > 20.f ? x : log1pf(expf(x)); }

struct GP {
    const __nv_bfloat16* A;
    const __nv_bfloat16* Wt;     // [N][K] bf16
    const float* bias;
    const float* add1;
    const float* add2;
    const float* cw;
    const float* cb;
    float* outf;
    __nv_bfloat16* outh;
};

__device__ __forceinline__ void mma_bf16(float* d, const uint32_t* a,
                                         uint32_t b0, uint32_t b1)
{
    asm volatile(
        "mma.sync.aligned.m16n8k16.row.col.f32.bf16.bf16.f32 "
        "{%0,%1,%2,%3}, {%4,%5,%6,%7}, {%8,%9}, {%0,%1,%2,%3};\n"
        : "+f"(d[0]), "+f"(d[1]), "+f"(d[2]), "+f"(d[3])
        : "r"(a[0]), "r"(a[1]), "r"(a[2]), "r"(a[3]), "r"(b0), "r"(b1));
}

// swizzled 16B-chunk address within a [128][32]bf16 tile
__device__ __forceinline__ uint32_t sw_addr(uint32_t base, int r, int c)
{
    return base + (uint32_t)((r*4 + (c ^ ((r>>1)&3))) << 4);
}

__device__ __forceinline__ void cp16(uint32_t smem, const void* gmem)
{
    asm volatile("cp.async.cg.shared.global [%0], [%1], 16;\n" :: "r"(smem), "l"(gmem));
}

template<int N, int EPI>
__device__ __forceinline__ void epi_store(const GP& p, int t, int c,
                                          float v0, float v1, int Ttot)
{
    if (t >= Ttot) return;
    if (EPI == 0) {
        p.outh[(size_t)t*N + c]   = __float2bfloat16(v0);
        p.outh[(size_t)t*N + c+1] = __float2bfloat16(v1);
    }
    if (EPI == 1) {
        v0 = gelu_t(v0 + __ldg(p.bias + c));
        v1 = gelu_t(v1 + __ldg(p.bias + c+1));
        p.outh[(size_t)t*N + c]   = __float2bfloat16(v0);
        p.outh[(size_t)t*N + c+1] = __float2bfloat16(v1);
    }
    if (EPI == 2) {
        p.outf[(size_t)t*256 + c]   = v0 + __ldg(p.bias + c)   + p.add1[(size_t)t*256 + c];
        p.outf[(size_t)t*256 + c+1] = v1 + __ldg(p.bias + c+1) + p.add1[(size_t)t*256 + c+1];
    }
    if (EPI == 3) {
        p.outf[(size_t)t*256 + c]   = v0;
        p.outf[(size_t)t*256 + c+1] = v1;
    }
    if (EPI == 4) {
        if (c < 512) {
            v0 = silu_f(fmaf(v0, __ldg(p.cw + c),   __ldg(p.cb + c)));
            v1 = silu_f(fmaf(v1, __ldg(p.cw + c+1), __ldg(p.cb + c+1)));
        } else {
            v0 = silu_f(v0);
            v1 = silu_f(v1);
        }
        p.outh[(size_t)t*1024 + c]   = __float2bfloat16(v0);
        p.outh[(size_t)t*1024 + c+1] = __float2bfloat16(v1);
    }
    if (EPI == 5) {
        p.outf[(size_t)t*256 + c]   = v0 + __ldg(p.bias + c)
                                         + p.add1[(size_t)t*256 + c] + p.add2[(size_t)t*256 + c];
        p.outf[(size_t)t*256 + c+1] = v1 + __ldg(p.bias + c+1)
                                         + p.add1[(size_t)t*256 + c+1] + p.add2[(size_t)t*256 + c+1];
    }
}

template<int K, int N, int EPI>
__global__ void __launch_bounds__(256) gemm_tc(GP p, int Ttot)
{
    __shared__ __nv_bfloat16 As[2][128*32];
    __shared__ __nv_bfloat16 Bs[2][128*32];
    const int tid  = threadIdx.x;
    const int lane = tid & 31;
    const int wid  = tid >> 5;
    const int wm = wid & 3;
    const int wn = wid >> 2;
    const int mBase = blockIdx.y * 128;
    const int nBase = blockIdx.x * 128;
    const int g  = lane >> 2;
    const int tq = lane & 3;
    const int NT_TILES = K / 32;

    const uint32_t baseA0 = (uint32_t)__cvta_generic_to_shared(&As[0][0]);
    const uint32_t baseA1 = (uint32_t)__cvta_generic_to_shared(&As[1][0]);
    const uint32_t baseB0 = (uint32_t)__cvta_generic_to_shared(&Bs[0][0]);
    const uint32_t baseB1 = (uint32_t)__cvta_generic_to_shared(&Bs[1][0]);

    // this thread's two staging chunks: idx = tid, tid+256  -> (r, c)
    const int r0s = tid >> 2,        c0s = tid & 3;
    const int r1s = (tid+256) >> 2,  c1s = tid & 3;
    int gr0 = mBase + r0s; if (gr0 >= Ttot) gr0 = Ttot - 1;
    int gr1 = mBase + r1s; if (gr1 >= Ttot) gr1 = Ttot - 1;
    const __nv_bfloat16* a0p = p.A  + (size_t)gr0*K          + c0s*8;
    const __nv_bfloat16* a1p = p.A  + (size_t)gr1*K          + c1s*8;
    const __nv_bfloat16* b0p = p.Wt + (size_t)(nBase+r0s)*K  + c0s*8;
    const __nv_bfloat16* b1p = p.Wt + (size_t)(nBase+r1s)*K  + c1s*8;

    float acc[2][8][4];
    for (int a = 0; a < 2; ++a)
        for (int b = 0; b < 8; ++b)
            for (int c = 0; c < 4; ++c)
                acc[a][b][c] = 0.f;

    // prefetch tile 0
    {
        cp16(sw_addr(baseA0, r0s, c0s), a0p);
        cp16(sw_addr(baseA0, r1s, c1s), a1p);
        cp16(sw_addr(baseB0, r0s, c0s), b0p);
        cp16(sw_addr(baseB0, r1s, c1s), b1p);
        asm volatile("cp.async.commit_group;\n");
    }

    for (int t = 0; t < NT_TILES; ++t) {
        if (t + 1 < NT_TILES) {
            const int koff = (t+1)*32;
            const uint32_t bA = ((t+1)&1) ? baseA1 : baseA0;
            const uint32_t bB = ((t+1)&1) ? baseB1 : baseB0;
            cp16(sw_addr(bA, r0s, c0s), a0p + koff);
            cp16(sw_addr(bA, r1s, c1s), a1p + koff);
            cp16(sw_addr(bB, r0s, c0s), b0p + koff);
            cp16(sw_addr(bB, r1s, c1s), b1p + koff);
            asm volatile("cp.async.commit_group;\n");
            asm volatile("cp.async.wait_group 1;\n");
        } else {
            asm volatile("cp.async.wait_group 0;\n");
        }
        __syncthreads();

        const uint32_t bA = (t&1) ? baseA1 : baseA0;
        const uint32_t bB = (t&1) ? baseB1 : baseB0;

        for (int ks = 0; ks < 2; ++ks) {
            const int c0 = ks*2;
            uint32_t af[2][4];
            for (int mi = 0; mi < 2; ++mi) {
                const int rr = wm*32 + mi*16 + (lane & 15);
                const int cc = c0 + (lane >> 4);
                uint32_t addr = sw_addr(bA, rr, cc);
                asm volatile("ldmatrix.sync.aligned.m8n8.x4.shared.b16 {%0,%1,%2,%3}, [%4];\n"
                    : "=r"(af[mi][0]), "=r"(af[mi][1]), "=r"(af[mi][2]), "=r"(af[mi][3])
                    : "r"(addr));
            }
            uint32_t bf[4][4];
            for (int nb4 = 0; nb4 < 4; ++nb4) {
                const int midx = lane >> 3;
                const int rr = wn*64 + nb4*16 + (midx>>1)*8 + (lane & 7);
                const int cc = c0 + (midx & 1);
                uint32_t addr = sw_addr(bB, rr, cc);
                asm volatile("ldmatrix.sync.aligned.m8n8.x4.shared.b16 {%0,%1,%2,%3}, [%4];\n"
                    : "=r"(bf[nb4][0]), "=r"(bf[nb4][1]), "=r"(bf[nb4][2]), "=r"(bf[nb4][3])
                    : "r"(addr));
            }
            for (int ni = 0; ni < 8; ++ni) {
                const int nb4 = ni >> 1;
                const int h   = ni & 1;
                uint32_t b0 = bf[nb4][h*2];
                uint32_t b1 = bf[nb4][h*2+1];
                mma_bf16(acc[0][ni], af[0], b0, b1);
                mma_bf16(acc[1][ni], af[1], b0, b1);
            }
        }
        __syncthreads();
    }

    for (int mi = 0; mi < 2; ++mi) {
        const int r0 = mBase + wm*32 + mi*16 + g;
        for (int ni = 0; ni < 8; ++ni) {
            const int c0 = nBase + wn*64 + ni*8 + 2*tq;
            epi_store<N,EPI>(p, r0,   c0, acc[mi][ni][0], acc[mi][ni][1], Ttot);
            epi_store<N,EPI>(p, r0+8, c0, acc[mi][ni][2], acc[mi][ni][3], Ttot);
        }
    }
}

// ---- weight transpose: out[n][k] = bf16(W[k][n]) ---------------------------
__global__ void k_wt(const float* W, __nv_bfloat16* out, int K, int N)
{
    __shared__ float t[32][33];
    const int k0 = blockIdx.y*32;
    const int n0 = blockIdx.x*32;
    const int tx = threadIdx.x;
    const int ty = threadIdx.y;
    for (int i = ty; i < 32; i += 8)
        t[i][tx] = W[(size_t)(k0+i)*N + n0 + tx];
    __syncthreads();
    for (int i = ty; i < 32; i += 8)
        out[(size_t)(n0+i)*K + k0 + tx] = __float2bfloat16(t[tx][i]);
}

// ============================================================================
__device__ __forceinline__ void build_ahat(float* ah, int tid, int nthr)
{
    for (int t = tid; t < 289; t += nthr) {
        int i = t/17;
        int j = t - i*17;
        ah[t] = ((c_adj[i]>>j)&1) ? rsqrtf(c_deg[i]*c_deg[j]) : 0.f;
    }
}

__device__ __forceinline__ void ln_rows_f32(const float* src, float* dst,
                                            const float* g, const float* b, int nthr)
{
    const int w = threadIdx.x >> 5;
    const int lane = threadIdx.x & 31;
    for (int l = w; l < 17; l += nthr/32) {
        const float* row = src + l*256;
        float s = 0.f;
        for (int i = 0; i < 8; ++i) s += row[lane + 32*i];
        for (int o = 16; o; o >>= 1) s += __shfl_xor_sync(0xffffffffu, s, o);
        const float m = s * (1.f/256.f);
        float v = 0.f;
        for (int i = 0; i < 8; ++i) { float d = row[lane+32*i]-m; v = fmaf(d,d,v); }
        for (int o = 16; o; o >>= 1) v += __shfl_xor_sync(0xffffffffu, v, o);
        const float r = rsqrtf(v*(1.f/256.f) + 1e-5f);
        for (int i = 0; i < 8; ++i) {
            int c = lane + 32*i;
            dst[l*256+c] = (row[c]-m)*r*__ldg(g+c) + __ldg(b+c);
        }
    }
}

__device__ __forceinline__ void ln_rows_bf16(const float* src, __nv_bfloat16* dst,
                                             const float* g, const float* b, int nthr)
{
    const int w = threadIdx.x >> 5;
    const int lane = threadIdx.x & 31;
    for (int l = w; l < 17; l += nthr/32) {
        const float* row = src + l*256;
        float s = 0.f;
        for (int i = 0; i < 8; ++i) s += row[lane + 32*i];
        for (int o = 16; o; o >>= 1) s += __shfl_xor_sync(0xffffffffu, s, o);
        const float m = s * (1.f/256.f);
        float v = 0.f;
        for (int i = 0; i < 8; ++i) { float d = row[lane+32*i]-m; v = fmaf(d,d,v); }
        for (int o = 16; o; o >>= 1) v += __shfl_xor_sync(0xffffffffu, v, o);
        const float r = rsqrtf(v*(1.f/256.f) + 1e-5f);
        for (int i = 0; i < 8; ++i) {
            int c = lane + 32*i;
            dst[(size_t)l*256+c] = __float2bfloat16((row[c]-m)*r*__ldg(g+c) + __ldg(b+c));
        }
    }
}

__global__ void __launch_bounds__(256) k_pre(const float* x, const float* g, const float* bv)
{
    __shared__ float xs[17*256];
    __shared__ float cur[17*256];
    __shared__ float ah[289];
    const int b = blockIdx.x;
    const int tid = threadIdx.x;
    const float4* xp = reinterpret_cast<const float4*>(x + (size_t)b*4352);
    for (int i = tid; i < 1088; i += 256) reinterpret_cast<float4*>(xs)[i] = xp[i];
    build_ahat(ah, tid, 256);
    __syncthreads();
    ln_rows_f32(xs, cur, g, bv, 256);
    __syncthreads();
    const int d = tid;
    float v[17];
    for (int j = 0; j < 17; ++j) v[j] = cur[j*256 + d];
    for (int i = 0; i < 17; ++i) {
        float a = 0.f;
        for (int j = 0; j < 17; ++j) a = fmaf(ah[i*17+j], v[j], a);
        g_bufD[((size_t)b*17 + i)*256 + d] = __float2bfloat16(a);
    }
}

__global__ void __launch_bounds__(256) k_mid1()
{
    __shared__ float h[17*512];
    __shared__ float ah[289];
    const int b = blockIdx.x;
    const int tid = threadIdx.x;
    const __nv_bfloat16* ip = g_bufC + (size_t)b*8704;
    for (int i = tid; i < 8704; i += 256) h[i] = __bfloat162float(ip[i]);
    build_ahat(ah, tid, 256);
    __syncthreads();
    for (int half = 0; half < 2; ++half) {
        const int d = tid + half*256;
        float v[17];
        for (int j = 0; j < 17; ++j) v[j] = h[j*512 + d];
        for (int i = 0; i < 17; ++i) {
            float a = 0.f;
            for (int j = 0; j < 17; ++j) a = fmaf(ah[i*17+j], v[j], a);
            g_bufB[(size_t)b*8704 + (size_t)i*512 + d] = __float2bfloat16(a);
        }
    }
}

__global__ void __launch_bounds__(256) k_mid2(const float* bp, const float* g, const float* bv)
{
    __shared__ float xs[17*256];
    const int b = blockIdx.x;
    const int tid = threadIdx.x;
    for (int i = tid; i < 4352; i += 256) {
        int l = i >> 8;
        int d = i & 255;
        xs[i] = g_res1[(size_t)b*4352 + c_hop[l]*256 + d] + __ldg(bp + c_bpe[l]*256 + d);
    }
    __syncthreads();
    ln_rows_bf16(xs, g_bufD + (size_t)b*4352, g, bv, 256);
}

__global__ void __launch_bounds__(256) k_mid3(const float* g, const float* bv)
{
    __shared__ float r2[17*256];
    const int b = blockIdx.x;
    const int tid = threadIdx.x;
    for (int i = tid; i < 4352; i += 256) {
        int l = i >> 8;
        int d = i & 255;
        float v = 2.f*g_res1[(size_t)b*4352 + i] + g_tmpf[(size_t)b*4352 + c_graph[l]*256 + d];
        r2[i] = v;
        g_res2[(size_t)b*4352 + i] = v;
    }
    __syncthreads();
    ln_rows_bf16(r2, g_bufD + (size_t)b*4352, g, bv, 256);
}

__global__ void __launch_bounds__(256) k_ln2(const float* g, const float* bv)
{
    __shared__ float xs[17*256];
    const int b = blockIdx.x;
    const int tid = threadIdx.x;
    const float4* xp = reinterpret_cast<const float4*>(g_x1 + (size_t)b*4352);
    for (int i = tid; i < 1088; i += 256) reinterpret_cast<float4*>(xs)[i] = xp[i];
    __syncthreads();
    ln_rows_bf16(xs, g_bufD + (size_t)b*4352, g, bv, 256);
}

__global__ void __launch_bounds__(512) k_scan(const float* x_proj_w,
                                              const float* dt_proj_w,
                                              const float* dt_proj_b,
                                              const float* A_log,
                                              const float* Dpv)
{
    extern __shared__ float sm[];
    float* xm  = sm;
    float* zs  = sm + 8704;
    float* dbl = sm + 17408;
    const int b = blockIdx.x;
    const int tid = threadIdx.x;
    for (int i = tid; i < 8704; i += 512) {
        int l = i >> 9;
        int d = i & 511;
        const __nv_bfloat16* base = g_bufA + ((size_t)b*17 + l)*1024;
        xm[i] = __bfloat162float(base[d]);
        zs[i] = __bfloat162float(base[512 + d]);
    }
    __syncthreads();
    if (tid < 408) {
        int l = tid/24;
        int n = tid - l*24;
        const float* xr = xm + l*512;
        float a = 0.f;
        for (int k = 0; k < 512; ++k) a = fmaf(xr[k], __ldg(x_proj_w + k*24 + n), a);
        dbl[tid] = a;
    }
    __syncthreads();
    const int d = tid;
    float negA[4];
    float h[4] = {0.f,0.f,0.f,0.f};
    float wdt[16];
    for (int s = 0; s < 4; ++s) negA[s] = -expf(__ldg(A_log + d*4 + s));
    for (int r = 0; r < 16; ++r) wdt[r] = __ldg(dt_proj_w + r*512 + d);
    const float dpb = __ldg(dt_proj_b + d);
    const float Dp  = __ldg(Dpv + d);
    for (int l = 0; l < 17; ++l) {
        const float* dl = dbl + l*24;
        float t0 = dpb;
        for (int r = 0; r < 16; ++r) t0 = fmaf(dl[r], wdt[r], t0);
        const float dt = softplus_f(t0);
        const float xv = xm[l*512 + d];
        float y = 0.f;
        for (int s = 0; s < 4; ++s) {
            const float Bv = dl[16+s];
            const float Cv = dl[20+s];
            h[s] = fmaf(expf(dt*negA[s]), h[s], dt*Bv*xv);
            y = fmaf(h[s], Cv, y);
        }
        y = fmaf(Dp, xv, y);
        g_bufC[((size_t)b*17 + l)*512 + d] = __float2bfloat16(y * zs[l*512 + d]);
    }
}

__global__ void __launch_bounds__(512) k_attn()
{
    extern __shared__ float s[];
    const int b = blockIdx.x;
    const int tid = threadIdx.x;
    const __nv_bfloat16* qp = g_bufB + (size_t)b*13056;
    for (int i = tid; i < 13056; i += 512) s[i] = __bfloat162float(qp[i]);
    __syncthreads();
    const int lane = tid & 31;
    const int w = tid >> 5;
    const float scale = 0.17677669529663687f;
    for (int task = w; task < 136; task += 16) {
        const int q = task >> 3;
        const int hh = task & 7;
        const int off = hh*32 + lane;
        const float qj = s[q*768 + off];
        float sc[17];
        float mx = -1e30f;
        for (int k = 0; k < 17; ++k) {
            float pv = qj * s[k*768 + 256 + off];
            for (int o = 16; o; o >>= 1) pv += __shfl_xor_sync(0xffffffffu, pv, o);
            pv *= scale;
            sc[k] = pv;
            mx = fmaxf(mx, pv);
        }
        float sum = 0.f;
        for (int k = 0; k < 17; ++k) { sc[k] = expf(sc[k]-mx); sum += sc[k]; }
        const float inv = 1.f/sum;
        float acc = 0.f;
        for (int k = 0; k < 17; ++k)
            acc = fmaf(sc[k]*inv, s[k*768 + 512 + off], acc);
        g_bufD[((size_t)b*17 + q)*256 + off] = __float2bfloat16(acc);
    }
}

// ============================================================================
extern "C" void kernel_launch(void* const* d_in, const int* in_sizes, int n_in,
                              void* d_out, int out_size)
{
    const float *x          = (const float*)d_in[0];
    const float *gcn_ln_g   = (const float*)d_in[1];
    const float *gcn_ln_b   = (const float*)d_in[2];
    const float *gcn_w1     = (const float*)d_in[3];
    const float *gcn_b1     = (const float*)d_in[4];
    const float *gcn_w2     = (const float*)d_in[5];
    const float *gcn_b2     = (const float*)d_in[6];
    const float *bp         = (const float*)d_in[7];
    const float *ssm_ln_g   = (const float*)d_in[8];
    const float *ssm_ln_b   = (const float*)d_in[9];
    const float *in_proj_w  = (const float*)d_in[10];
    const float *conv_w     = (const float*)d_in[11];
    const float *conv_b     = (const float*)d_in[12];
    const float *x_proj_w   = (const float*)d_in[13];
    const float *dt_proj_w  = (const float*)d_in[14];
    const float *dt_proj_b  = (const float*)d_in[15];
    const float *A_log      = (const float*)d_in[16];
    const float *Dp         = (const float*)d_in[17];
    const float *out_proj_w = (const float*)d_in[18];
    const float *ln1_g      = (const float*)d_in[19];
    const float *ln1_b      = (const float*)d_in[20];
    const float *qkv_w      = (const float*)d_in[21];
    const float *attn_proj_w= (const float*)d_in[22];
    const float *attn_proj_b= (const float*)d_in[23];
    const float *ln2_g      = (const float*)d_in[24];
    const float *ln2_b      = (const float*)d_in[25];
    const float *mlp_w1     = (const float*)d_in[26];
    const float *mlp_b1     = (const float*)d_in[27];
    const float *mlp_w2     = (const float*)d_in[28];
    const float *mlp_b2     = (const float*)d_in[29];
    float* outp             = (float*)d_out;

    const int nb   = in_sizes[0] / 4352;
    const int Ttot = nb * 17;
    const int mT   = (Ttot + 127) / 128;

    __nv_bfloat16 *bufA = 0, *bufB = 0, *bufC = 0, *bufD = 0, *wt = 0;
    float *res1 = 0, *res2 = 0, *x1 = 0, *tmpf = 0;
    cudaGetSymbolAddress((void**)&bufA, g_bufA);
    cudaGetSymbolAddress((void**)&bufB, g_bufB);
    cudaGetSymbolAddress((void**)&bufC, g_bufC);
    cudaGetSymbolAddress((void**)&bufD, g_bufD);
    cudaGetSymbolAddress((void**)&res1, g_res1);
    cudaGetSymbolAddress((void**)&res2, g_res2);
    cudaGetSymbolAddress((void**)&x1,   g_x1);
    cudaGetSymbolAddress((void**)&tmpf, g_tmpf);
    cudaGetSymbolAddress((void**)&wt,   g_wt);

    // transposed weight layout offsets
    __nv_bfloat16* wt_gcn1 = wt;                 // [512][256]
    __nv_bfloat16* wt_gcn2 = wt + 131072;        // [256][512]
    __nv_bfloat16* wt_inp  = wt + 262144;        // [1024][256]
    __nv_bfloat16* wt_outp = wt + 524288;        // [256][512]
    __nv_bfloat16* wt_qkv  = wt + 655360;        // [768][256]
    __nv_bfloat16* wt_attn = wt + 851968;        // [256][256]
    __nv_bfloat16* wt_mlp1 = wt + 917504;        // [1024][256]
    __nv_bfloat16* wt_mlp2 = wt + 1179648;       // [256][1024]

    cudaFuncSetAttribute(k_scan, cudaFuncAttributeMaxDynamicSharedMemorySize, 17816*4);
    cudaFuncSetAttribute(k_attn, cudaFuncAttributeMaxDynamicSharedMemorySize, 13056*4);

    dim3 tb(32, 8);
    k_wt<<<dim3(512/32, 256/32), tb>>>(gcn_w1,      wt_gcn1, 256, 512);
    k_wt<<<dim3(256/32, 512/32), tb>>>(gcn_w2,      wt_gcn2, 512, 256);
    k_wt<<<dim3(1024/32,256/32), tb>>>(in_proj_w,   wt_inp,  256, 1024);
    k_wt<<<dim3(256/32, 512/32), tb>>>(out_proj_w,  wt_outp, 512, 256);
    k_wt<<<dim3(768/32, 256/32), tb>>>(qkv_w,       wt_qkv,  256, 768);
    k_wt<<<dim3(256/32, 256/32), tb>>>(attn_proj_w, wt_attn, 256, 256);
    k_wt<<<dim3(1024/32,256/32), tb>>>(mlp_w1,      wt_mlp1, 256, 1024);
    k_wt<<<dim3(256/32,1024/32), tb>>>(mlp_w2,      wt_mlp2, 1024, 256);

    // Stage A: GCN
    k_pre<<<nb, 256>>>(x, gcn_ln_g, gcn_ln_b);
    GP p1 = { bufD, wt_gcn1, gcn_b1, 0, 0, 0, 0, 0, bufC };
    gemm_tc<256,512,1><<<dim3(4, mT), 256>>>(p1, Ttot);
    k_mid1<<<nb, 256>>>();
    GP p2 = { bufB, wt_gcn2, gcn_b2, x, 0, 0, 0, res1, 0 };
    gemm_tc<512,256,2><<<dim3(2, mT), 256>>>(p2, Ttot);

    // Stage B: SSM
    k_mid2<<<nb, 256>>>(bp, ssm_ln_g, ssm_ln_b);
    GP p3 = { bufD, wt_inp, 0, 0, 0, conv_w, conv_b, 0, bufA };
    gemm_tc<256,1024,4><<<dim3(8, mT), 256>>>(p3, Ttot);
    k_scan<<<nb, 512, 17816*4>>>(x_proj_w, dt_proj_w, dt_proj_b, A_log, Dp);
    GP p4 = { bufC, wt_outp, 0, 0, 0, 0, 0, tmpf, 0 };
    gemm_tc<512,256,3><<<dim3(2, mT), 256>>>(p4, Ttot);
    k_mid3<<<nb, 256>>>(ln1_g, ln1_b);

    // Stage C: attention
    GP p5 = { bufD, wt_qkv, 0, 0, 0, 0, 0, 0, bufB };
    gemm_tc<256,768,0><<<dim3(6, mT), 256>>>(p5, Ttot);
    k_attn<<<nb, 512, 13056*4>>>();
    GP p6 = { bufD, wt_attn, attn_proj_b, res2, 0, 0, 0, x1, 0 };
    gemm_tc<256,256,2><<<dim3(2, mT), 256>>>(p6, Ttot);

    // Stage D: MLP
    k_ln2<<<nb, 256>>>(ln2_g, ln2_b);
    GP p7 = { bufD, wt_mlp1, mlp_b1, 0, 0, 0, 0, 0, bufA };
    gemm_tc<256,1024,1><<<dim3(8, mT), 256>>>(p7, Ttot);
    GP p8 = { bufA, wt_mlp2, mlp_b2, x1, res2, 0, 0, outp, 0 };
    gemm_tc<1024,256,5><<<dim3(2, mT), 256>>>(p8, Ttot);
}